// round 16
// baseline (speedup 1.0000x reference)
#include <cuda_runtime.h>
#include <cstdint>

// Problem constants (BATCH=4, SEQ=4096, DIM=1024)
#define B 4
#define L 4096
#define D 1024
#define C  64                 // chunk length
#define NC 64                 // chunks along L (NC*C == L)
#define TPB 256               // threads per block, 2 dims each
#define DBLK 2                // dim blocks (DBLK*TPB*2 == D)
#define G 4                   // load-group size

// Scratch (__device__ globals: allocation-free rule). 2 MB each.
__device__ float2 g_totals[B * NC * D];
__device__ float2 g_carry [B * NC * D];

__device__ __forceinline__ float2 cmul(float2 u, float2 v) {
    return make_float2(fmaf(u.x, v.x, -u.y * v.y), fmaf(u.x, v.y, u.y * v.x));
}

__device__ __forceinline__ float2 decay(float r, float im) {
    float mag = sqrtf(fmaf(r, r, im * im));
    float s = __expf(-mag) / mag;
    return make_float2(r * s, im * s);
}

// ---- K1: zero-init local chunk scans -> totals. 2 dims/thread, group-4 MLP. ----
__global__ void __launch_bounds__(TPB, 4)
k1_totals(const float* __restrict__ x,
          const float* __restrict__ pr, const float* __restrict__ pi,
          const float* __restrict__ ir, const float* __restrict__ ii)
{
    const int d0    = (blockIdx.x * TPB + threadIdx.x) * 2;
    const int chunk = blockIdx.y;
    const int b     = blockIdx.z;

    const float* xp = x + ((size_t)(b * L + chunk * C)) * D + d0;

    const float2 a0 = decay(pr[d0],     pi[d0]);
    const float2 a1 = decay(pr[d0 + 1], pi[d0 + 1]);
    const float2 cre = *(const float2*)(ir + d0);
    const float2 cim = *(const float2*)(ii + d0);

    float h0r = 0.f, h0i = 0.f, h1r = 0.f, h1i = 0.f;

#pragma unroll
    for (int g = 0; g < C / G; g++) {
        float2 xv[G];
#pragma unroll
        for (int k = 0; k < G; k++)
            xv[k] = *(const float2*)(xp + (size_t)(g * G + k) * D);
#pragma unroll
        for (int k = 0; k < G; k++) {
            float n0r = fmaf(a0.x, h0r, fmaf(-a0.y, h0i, cre.x * xv[k].x));
            float n0i = fmaf(a0.x, h0i, fmaf( a0.y, h0r, cim.x * xv[k].x));
            float n1r = fmaf(a1.x, h1r, fmaf(-a1.y, h1i, cre.y * xv[k].y));
            float n1i = fmaf(a1.x, h1i, fmaf( a1.y, h1r, cim.y * xv[k].y));
            h0r = n0r; h0i = n0i; h1r = n1r; h1i = n1i;
        }
    }
    *(float4*)&g_totals[((size_t)b * NC + chunk) * D + d0] =
        make_float4(h0r, h0i, h1r, h1i);
}

// ---- K2: serial carry propagation per (b, 2 dims); float4 totals; default stores. ----
__global__ void __launch_bounds__(512)
k2_carries(const float* __restrict__ pr, const float* __restrict__ pi,
           const float* __restrict__ lr, const float* __restrict__ li)
{
    const int gid = blockIdx.x * blockDim.x + threadIdx.x;   // 0..2047
    if (gid >= B * D / 2) return;
    const int b  = gid / (D / 2);
    const int d0 = (gid % (D / 2)) * 2;

    float2 aA = decay(pr[d0],     pi[d0]);
    float2 aB = decay(pr[d0 + 1], pi[d0 + 1]);
#pragma unroll
    for (int k = 0; k < 6; k++) { aA = cmul(aA, aA); aB = cmul(aB, aB); }  // a^64

    float H0r = lr[b * D + d0],     H0i = li[b * D + d0];
    float H1r = lr[b * D + d0 + 1], H1i = li[b * D + d0 + 1];

#pragma unroll
    for (int base = 0; base < NC; base += 16) {
        float4 Tb[16];
#pragma unroll
        for (int k = 0; k < 16; k++)
            Tb[k] = __ldg((const float4*)&g_totals[((size_t)b * NC + base + k) * D + d0]);
#pragma unroll
        for (int k = 0; k < 16; k++) {
            *(float4*)&g_carry[((size_t)b * NC + base + k) * D + d0] =
                make_float4(H0r, H0i, H1r, H1i);   // default policy: stays L2-hot for K3
            float n0r = fmaf(aA.x, H0r, fmaf(-aA.y, H0i, Tb[k].x));
            float n0i = fmaf(aA.x, H0i, fmaf( aA.y, H0r, Tb[k].y));
            float n1r = fmaf(aB.x, H1r, fmaf(-aB.y, H1i, Tb[k].z));
            float n1i = fmaf(aB.x, H1i, fmaf( aB.y, H1r, Tb[k].w));
            H0r = n0r; H0i = n0i; H1r = n1r; H1i = n1i;
        }
    }
}

// ---- K3: exact scan seeded with carry; group-4 loads + streaming out stores. ----
__global__ void __launch_bounds__(TPB, 4)
k3_scan(const float* __restrict__ x,
        const float* __restrict__ pr, const float* __restrict__ pi,
        const float* __restrict__ ir, const float* __restrict__ ii,
        float* __restrict__ out)
{
    const int d0    = (blockIdx.x * TPB + threadIdx.x) * 2;
    const int chunk = blockIdx.y;
    const int b     = blockIdx.z;

    const size_t base = ((size_t)(b * L + chunk * C)) * D + d0;
    const float* xp = x + base;
    float* op = out + base;

    const float2 a0 = decay(pr[d0],     pi[d0]);
    const float2 a1 = decay(pr[d0 + 1], pi[d0 + 1]);
    const float2 cre = *(const float2*)(ir + d0);
    const float2 cim = *(const float2*)(ii + d0);

    float4 h0 = *(const float4*)&g_carry[((size_t)b * NC + chunk) * D + d0];
    float h0r = h0.x, h0i = h0.y, h1r = h0.z, h1i = h0.w;

#pragma unroll
    for (int g = 0; g < C / G; g++) {
        float2 xv[G];
#pragma unroll
        for (int k = 0; k < G; k++)
            xv[k] = *(const float2*)(xp + (size_t)(g * G + k) * D);
#pragma unroll
        for (int k = 0; k < G; k++) {
            float n0r = fmaf(a0.x, h0r, fmaf(-a0.y, h0i, cre.x * xv[k].x));
            float n0i = fmaf(a0.x, h0i, fmaf( a0.y, h0r, cim.x * xv[k].x));
            float n1r = fmaf(a1.x, h1r, fmaf(-a1.y, h1i, cre.y * xv[k].y));
            float n1i = fmaf(a1.x, h1i, fmaf( a1.y, h1r, cim.y * xv[k].y));
            h0r = n0r; h0i = n0i; h1r = n1r; h1i = n1i;
            __stcs((float2*)(op + (size_t)(g * G + k) * D), make_float2(h0r, h1r));
        }
    }
}

extern "C" void kernel_launch(void* const* d_in, const int* in_sizes, int n_in,
                              void* d_out, int out_size) {
    const float* x    = (const float*)d_in[0];
    const float* p_re = (const float*)d_in[1];
    const float* p_im = (const float*)d_in[2];
    const float* i_re = (const float*)d_in[3];
    const float* i_im = (const float*)d_in[4];
    const float* lc_r = (const float*)d_in[5];
    const float* lc_i = (const float*)d_in[6];
    float* out = (float*)d_out;

    dim3 grid(DBLK, NC, B);   // (2, 64, 4) = 512 blocks x 256 threads
    k1_totals<<<grid, TPB>>>(x, p_re, p_im, i_re, i_im);
    k2_carries<<<(B * D / 2 + 511) / 512, 512>>>(p_re, p_im, lc_r, lc_i);
    k3_scan<<<grid, TPB>>>(x, p_re, p_im, i_re, i_im, out);
}

// round 17
// speedup vs baseline: 1.1664x; 1.1664x over previous
#include <cuda_runtime.h>
#include <cstdint>

// Problem constants (BATCH=4, SEQ=4096, DIM=1024)
#define B 4
#define L 4096
#define D 1024
#define C  64                 // chunk length
#define NC 64                 // chunks along L (NC*C == L)
#define TPB 256               // K1 threads per block, 2 dims each
#define DBLK 2                // K1 dim blocks
#define G 4                   // load-group size

// K3 shape: 4 dims/thread, float4 pipeline
#define TPB3 128
#define DBLK3 2               // DBLK3*TPB3*4 == D

// Scratch (__device__ globals: allocation-free rule). 2 MB each.
__device__ float2 g_totals[B * NC * D];
__device__ float2 g_carry [B * NC * D];

__device__ __forceinline__ float2 cmul(float2 u, float2 v) {
    return make_float2(fmaf(u.x, v.x, -u.y * v.y), fmaf(u.x, v.y, u.y * v.x));
}

__device__ __forceinline__ float2 decay(float r, float im) {
    float mag = sqrtf(fmaf(r, r, im * im));
    float s = __expf(-mag) / mag;
    return make_float2(r * s, im * s);
}

// ---- K1: zero-init local chunk scans -> totals. 2 dims/thread, group-4 MLP. (R9) ----
__global__ void __launch_bounds__(TPB, 4)
k1_totals(const float* __restrict__ x,
          const float* __restrict__ pr, const float* __restrict__ pi,
          const float* __restrict__ ir, const float* __restrict__ ii)
{
    const int d0    = (blockIdx.x * TPB + threadIdx.x) * 2;
    const int chunk = blockIdx.y;
    const int b     = blockIdx.z;

    const float* xp = x + ((size_t)(b * L + chunk * C)) * D + d0;

    const float2 a0 = decay(pr[d0],     pi[d0]);
    const float2 a1 = decay(pr[d0 + 1], pi[d0 + 1]);
    const float2 cre = *(const float2*)(ir + d0);
    const float2 cim = *(const float2*)(ii + d0);

    float h0r = 0.f, h0i = 0.f, h1r = 0.f, h1i = 0.f;

#pragma unroll
    for (int g = 0; g < C / G; g++) {
        float2 xv[G];
#pragma unroll
        for (int k = 0; k < G; k++)
            xv[k] = *(const float2*)(xp + (size_t)(g * G + k) * D);
#pragma unroll
        for (int k = 0; k < G; k++) {
            float n0r = fmaf(a0.x, h0r, fmaf(-a0.y, h0i, cre.x * xv[k].x));
            float n0i = fmaf(a0.x, h0i, fmaf( a0.y, h0r, cim.x * xv[k].x));
            float n1r = fmaf(a1.x, h1r, fmaf(-a1.y, h1i, cre.y * xv[k].y));
            float n1i = fmaf(a1.x, h1i, fmaf( a1.y, h1r, cim.y * xv[k].y));
            h0r = n0r; h0i = n0i; h1r = n1r; h1i = n1i;
        }
    }
    *(float4*)&g_totals[((size_t)b * NC + chunk) * D + d0] =
        make_float4(h0r, h0i, h1r, h1i);
}

// ---- K2: serial carry propagation per (b,d) pair; batched prefetch. (R9) ----
__global__ void __launch_bounds__(512)
k2_carries(const float* __restrict__ pr, const float* __restrict__ pi,
           const float* __restrict__ lr, const float* __restrict__ li)
{
    const int idx = blockIdx.x * blockDim.x + threadIdx.x;   // 0..B*D-1
    if (idx >= B * D) return;
    const int b = idx >> 10;       // /D
    const int d = idx & (D - 1);   // %D

    float2 a = decay(pr[d], pi[d]);
    float2 aC = a;
#pragma unroll
    for (int k = 0; k < 6; k++) aC = cmul(aC, aC);   // a^64

    float Hr = lr[idx], Hi = li[idx];
#pragma unroll
    for (int base = 0; base < NC; base += 16) {
        float2 Tb[16];
#pragma unroll
        for (int k = 0; k < 16; k++)
            Tb[k] = __ldg((const float2*)&g_totals[((size_t)b * NC + base + k) * D + d]);
#pragma unroll
        for (int k = 0; k < 16; k++) {
            g_carry[((size_t)b * NC + base + k) * D + d] = make_float2(Hr, Hi);
            float nr = fmaf(aC.x, Hr, fmaf(-aC.y, Hi, Tb[k].x));
            float ni = fmaf(aC.x, Hi, fmaf( aC.y, Hr, Tb[k].y));
            Hr = nr; Hi = ni;
        }
    }
}

// ---- K3: exact scan, 4 dims/thread, float4 loads + float4 streaming stores. ----
__global__ void __launch_bounds__(TPB3, 8)
k3_scan(const float* __restrict__ x,
        const float* __restrict__ pr, const float* __restrict__ pi,
        const float* __restrict__ ir, const float* __restrict__ ii,
        float* __restrict__ out)
{
    const int d0    = (blockIdx.x * TPB3 + threadIdx.x) * 4;
    const int chunk = blockIdx.y;
    const int b     = blockIdx.z;

    const size_t base = ((size_t)(b * L + chunk * C)) * D + d0;
    const float* xp = x + base;
    float* op = out + base;

    const float2 a0 = decay(pr[d0],     pi[d0]);
    const float2 a1 = decay(pr[d0 + 1], pi[d0 + 1]);
    const float2 a2 = decay(pr[d0 + 2], pi[d0 + 2]);
    const float2 a3 = decay(pr[d0 + 3], pi[d0 + 3]);
    const float4 cre = *(const float4*)(ir + d0);
    const float4 cim = *(const float4*)(ii + d0);

    const float2* cp = &g_carry[((size_t)b * NC + chunk) * D + d0];
    float4 hA = *(const float4*)(cp);
    float4 hB = *(const float4*)(cp + 2);
    float h0r = hA.x, h0i = hA.y, h1r = hA.z, h1i = hA.w;
    float h2r = hB.x, h2i = hB.y, h3r = hB.z, h3i = hB.w;

#pragma unroll
    for (int g = 0; g < C / G; g++) {
        float4 xv[G];
#pragma unroll
        for (int k = 0; k < G; k++)
            xv[k] = *(const float4*)(xp + (size_t)(g * G + k) * D);
#pragma unroll
        for (int k = 0; k < G; k++) {
            float n0r = fmaf(a0.x, h0r, fmaf(-a0.y, h0i, cre.x * xv[k].x));
            float n0i = fmaf(a0.x, h0i, fmaf( a0.y, h0r, cim.x * xv[k].x));
            float n1r = fmaf(a1.x, h1r, fmaf(-a1.y, h1i, cre.y * xv[k].y));
            float n1i = fmaf(a1.x, h1i, fmaf( a1.y, h1r, cim.y * xv[k].y));
            float n2r = fmaf(a2.x, h2r, fmaf(-a2.y, h2i, cre.z * xv[k].z));
            float n2i = fmaf(a2.x, h2i, fmaf( a2.y, h2r, cim.z * xv[k].z));
            float n3r = fmaf(a3.x, h3r, fmaf(-a3.y, h3i, cre.w * xv[k].w));
            float n3i = fmaf(a3.x, h3i, fmaf( a3.y, h3r, cim.w * xv[k].w));
            h0r = n0r; h0i = n0i; h1r = n1r; h1i = n1i;
            h2r = n2r; h2i = n2i; h3r = n3r; h3i = n3i;
            __stcs((float4*)(op + (size_t)(g * G + k) * D),
                   make_float4(h0r, h1r, h2r, h3r));
        }
    }
}

extern "C" void kernel_launch(void* const* d_in, const int* in_sizes, int n_in,
                              void* d_out, int out_size) {
    const float* x    = (const float*)d_in[0];
    const float* p_re = (const float*)d_in[1];
    const float* p_im = (const float*)d_in[2];
    const float* i_re = (const float*)d_in[3];
    const float* i_im = (const float*)d_in[4];
    const float* lc_r = (const float*)d_in[5];
    const float* lc_i = (const float*)d_in[6];
    float* out = (float*)d_out;

    dim3 grid1(DBLK, NC, B);    // (2, 64, 4) = 512 blocks x 256 threads
    k1_totals<<<grid1, TPB>>>(x, p_re, p_im, i_re, i_im);

    k2_carries<<<(B * D) / 512, 512>>>(p_re, p_im, lc_r, lc_i);

    dim3 grid3(DBLK3, NC, B);   // (2, 64, 4) = 512 blocks x 128 threads
    k3_scan<<<grid3, TPB3>>>(x, p_re, p_im, i_re, i_im, out);
}